// round 2
// baseline (speedup 1.0000x reference)
#include <cuda_runtime.h>

#define SEQ   4096
#define DIMD  1024
#define NHEAD 16
#define DHEAD 64
#define KPROJ 256
#define NB    4
#define MTOT  (NB*SEQ)

// scratch (no allocation allowed)
__device__ float g_Q [MTOT*(long)DIMD];
__device__ float g_AO[MTOT*(long)DIMD];
__device__ float g_XE[NB*DIMD*KPROJ];
__device__ float g_XF[NB*DIMD*KPROJ];
__device__ float g_KE[NB*DIMD*KPROJ];
__device__ float g_VF[NB*DIMD*KPROJ];
__device__ float g_SS[2*KPROJ];

// ---------------- column sums of E and F ----------------
__global__ void colsum_k(const float* __restrict__ E, const float* __restrict__ F,
                         float* __restrict__ out)
{
    int c = threadIdx.x;
    const float* A = blockIdx.x ? F : E;
    float s = 0.f;
    #pragma unroll 8
    for (int r = 0; r < SEQ; r++) s += A[(long)r*KPROJ + c];
    out[blockIdx.x*KPROJ + c] = s;
}

// ---------------- generic SGEMM ----------------
// TA=false: C[M,N] = A[M,K] @ B[K,N]     (A row-major [M,K])
// TA=true : C[M,N] = A^T  @ B            (A stored [K,M])
// BIAS: 0 none; 1 C+=bv[n]; 2 C+=bu[m]*bv[n].  blockIdx.z batches via strides.
template<int BM,int BN,int BK,bool TA,int BIAS,int TM,int TN>
__global__ __launch_bounds__(256)
void sgemm(const float* __restrict__ A, const float* __restrict__ B,
           float* __restrict__ C, int M, int N, int K,
           long sA, long sB, long sC,
           const float* __restrict__ bu, const float* __restrict__ bv)
{
    __shared__ float As[2][BK][BM+4];
    __shared__ float Bs[2][BK][BN];
    const int tid = threadIdx.x;
    const int tx = tid & 15, ty = tid >> 4;
    const int bm = blockIdx.y*BM, bn = blockIdx.x*BN;
    A += (long)blockIdx.z*sA; B += (long)blockIdx.z*sB; C += (long)blockIdx.z*sC;

    constexpr int LA = BM*BK/1024, LB = BN*BK/1024;
    float4 ra[LA], rb[LB];

    auto fetch = [&](int t){
        const int k0 = t*BK;
        #pragma unroll
        for (int i = 0; i < LA; i++) {
            int idx = tid + i*256;
            if (TA) { int kr = idx/(BM/4), mc = (idx%(BM/4))*4;
                ra[i] = *(const float4*)(A + (long)(k0+kr)*M + bm + mc); }
            else    { int mr = idx/(BK/4), kc = (idx%(BK/4))*4;
                ra[i] = *(const float4*)(A + (long)(bm+mr)*K + k0 + kc); }
        }
        #pragma unroll
        for (int i = 0; i < LB; i++) {
            int idx = tid + i*256;
            int kr = idx/(BN/4), nc = (idx%(BN/4))*4;
            rb[i] = *(const float4*)(B + (long)(k0+kr)*N + bn + nc);
        }
    };
    auto stage = [&](int buf){
        #pragma unroll
        for (int i = 0; i < LA; i++) {
            int idx = tid + i*256;
            if (TA) { int kr = idx/(BM/4), mc = (idx%(BM/4))*4;
                *(float4*)&As[buf][kr][mc] = ra[i]; }
            else    { int mr = idx/(BK/4), kc = (idx%(BK/4))*4;
                As[buf][kc+0][mr] = ra[i].x; As[buf][kc+1][mr] = ra[i].y;
                As[buf][kc+2][mr] = ra[i].z; As[buf][kc+3][mr] = ra[i].w; }
        }
        #pragma unroll
        for (int i = 0; i < LB; i++) {
            int idx = tid + i*256;
            int kr = idx/(BN/4), nc = (idx%(BN/4))*4;
            *(float4*)&Bs[buf][kr][nc] = rb[i];
        }
    };

    float acc[TM][TN] = {};
    fetch(0); stage(0); __syncthreads();
    const int nT = K/BK;
    for (int t = 0; t < nT; t++) {
        const int cur = t & 1;
        if (t+1 < nT) fetch(t+1);
        #pragma unroll
        for (int k = 0; k < BK; k++) {
            float av[TM], bw[TN];
            #pragma unroll
            for (int i = 0; i < TM; i += 4)
                *(float4*)&av[i] = *(const float4*)&As[cur][k][ty*TM + i];
            #pragma unroll
            for (int j = 0; j < TN; j += 4)
                *(float4*)&bw[j] = *(const float4*)&Bs[cur][k][tx*TN + j];
            #pragma unroll
            for (int i = 0; i < TM; i++)
                #pragma unroll
                for (int j = 0; j < TN; j++)
                    acc[i][j] += av[i]*bw[j];
        }
        __syncthreads();
        if (t+1 < nT) { stage(1-cur); __syncthreads(); }
    }

    #pragma unroll
    for (int i = 0; i < TM; i++) {
        const int r = bm + ty*TM + i;
        #pragma unroll
        for (int j = 0; j < TN; j += 4) {
            const int c = bn + tx*TN + j;
            float4 v = *(float4*)&acc[i][j];
            if (BIAS == 1) {
                float4 b4 = *(const float4*)(bv + c);
                v.x += b4.x; v.y += b4.y; v.z += b4.z; v.w += b4.w;
            } else if (BIAS == 2) {
                const float u = bu[r];
                float4 b4 = *(const float4*)(bv + c);
                v.x += u*b4.x; v.y += u*b4.y; v.z += u*b4.z; v.w += u*b4.w;
            }
            *(float4*)(C + (long)r*N + c) = v;
        }
    }
}

// ---------------- fused Linformer attention ----------------
// CTA = one (batch b, head h, 128-query tile). S = Q*kE*scale, softmax over
// 256 compressed keys, out = P*vF. kE/vF rows [(h*64+d)][m] contiguous 64x256.
__global__ __launch_bounds__(256)
void attn_k(const float* __restrict__ Q, const float* __restrict__ KE,
            const float* __restrict__ VF, float* __restrict__ O)
{
    extern __shared__ float sm[];
    float* Ksm = sm;               // [64][256]
    float* Vsm = sm + 64*256;      // [64][256]
    float* Qst = sm + 2*64*256;    // [64][136] Q^T; reused as Osm[128][68]
    const int tid = threadIdx.x;
    const int l0 = blockIdx.x*128, h = blockIdx.y, b = blockIdx.z;

    const float* kk = KE + ((long)b*DIMD + h*DHEAD)*KPROJ;
    const float* vv = VF + ((long)b*DIMD + h*DHEAD)*KPROJ;
    #pragma unroll
    for (int i = 0; i < 16; i++) {
        int idx = (tid + i*256)*4;
        *(float4*)(Ksm+idx) = *(const float4*)(kk+idx);
        *(float4*)(Vsm+idx) = *(const float4*)(vv+idx);
    }
    const float* qq = Q + (long)(b*SEQ + l0)*DIMD + h*DHEAD;
    #pragma unroll
    for (int i = 0; i < 8; i++) {
        int idx = tid + i*256;            // 0..2047
        int l = idx >> 4, dg = (idx & 15)*4;
        float4 v = *(const float4*)(qq + (long)l*DIMD + dg);
        Qst[(dg+0)*136 + l] = v.x; Qst[(dg+1)*136 + l] = v.y;
        Qst[(dg+2)*136 + l] = v.z; Qst[(dg+3)*136 + l] = v.w;
    }
    __syncthreads();

    const int mg = tid & 7, rg = tid >> 3;   // cols mg*4+c*32+i, rows rg*4..+3
    float acc[4][32];
    #pragma unroll
    for (int r = 0; r < 4; r++)
        #pragma unroll
        for (int j = 0; j < 32; j++) acc[r][j] = 0.f;

    for (int d = 0; d < 64; d++) {
        float4 qv = *(const float4*)(Qst + d*136 + rg*4);
        float qa[4] = {qv.x, qv.y, qv.z, qv.w};
        #pragma unroll
        for (int c = 0; c < 8; c++) {
            float4 kv = *(const float4*)(Ksm + d*256 + mg*4 + c*32);
            #pragma unroll
            for (int r = 0; r < 4; r++) {
                acc[r][c*4+0] += qa[r]*kv.x; acc[r][c*4+1] += qa[r]*kv.y;
                acc[r][c*4+2] += qa[r]*kv.z; acc[r][c*4+3] += qa[r]*kv.w;
            }
        }
    }

    // softmax over 256 (distributed across 8 mg lanes), normalization deferred
    float po[4];
    #pragma unroll
    for (int r = 0; r < 4; r++) {
        float mx = -1e30f;
        #pragma unroll
        for (int j = 0; j < 32; j++) { acc[r][j] *= 0.125f; mx = fmaxf(mx, acc[r][j]); }
        #pragma unroll
        for (int s = 1; s < 8; s <<= 1) mx = fmaxf(mx, __shfl_xor_sync(0xffffffffu, mx, s));
        float sum = 0.f;
        #pragma unroll
        for (int j = 0; j < 32; j++) { float e = __expf(acc[r][j]-mx); acc[r][j] = e; sum += e; }
        #pragma unroll
        for (int s = 1; s < 8; s <<= 1) sum += __shfl_xor_sync(0xffffffffu, sum, s);
        po[r] = 1.f/sum;
    }
    __syncthreads();   // Qst reads finished everywhere; safe to reuse as Osm

    for (int d = 0; d < 64; d++) {
        float part[4] = {0.f, 0.f, 0.f, 0.f};
        #pragma unroll
        for (int c = 0; c < 8; c++) {
            float4 v4 = *(const float4*)(Vsm + d*256 + mg*4 + c*32);
            #pragma unroll
            for (int r = 0; r < 4; r++)
                part[r] += acc[r][c*4+0]*v4.x + acc[r][c*4+1]*v4.y
                         + acc[r][c*4+2]*v4.z + acc[r][c*4+3]*v4.w;
        }
        #pragma unroll
        for (int r = 0; r < 4; r++) {
            #pragma unroll
            for (int s = 1; s < 8; s <<= 1) part[r] += __shfl_xor_sync(0xffffffffu, part[r], s);
            if (mg == 0) Qst[(rg*4+r)*68 + d] = part[r]*po[r];
        }
    }
    __syncthreads();

    float* Op = O + (long)(b*SEQ + l0)*DIMD + h*DHEAD;
    #pragma unroll
    for (int i = 0; i < 32; i++) {
        int idx = tid + i*256;            // 0..8191
        int l = idx >> 6, dd = idx & 63;
        Op[(long)l*DIMD + dd] = Qst[l*68 + dd];
    }
}

// ---------------- launch ----------------
extern "C" void kernel_launch(void* const* d_in, const int*, int,
                              void* d_out, int)
{
    const float* x  = (const float*)d_in[0];
    const float* Wq = (const float*)d_in[1];
    const float* bq = (const float*)d_in[2];
    const float* Wk = (const float*)d_in[3];
    const float* bk = (const float*)d_in[4];
    const float* Wv = (const float*)d_in[5];
    const float* bv = (const float*)d_in[6];
    const float* E  = (const float*)d_in[7];
    const float* F  = (const float*)d_in[8];
    const float* Wo = (const float*)d_in[9];
    const float* bo = (const float*)d_in[10];
    float* out = (float*)d_out;

    float *Q, *AO, *XE, *XF, *KE, *VF, *SS;
    cudaGetSymbolAddress((void**)&Q,  g_Q);
    cudaGetSymbolAddress((void**)&AO, g_AO);
    cudaGetSymbolAddress((void**)&XE, g_XE);
    cudaGetSymbolAddress((void**)&XF, g_XF);
    cudaGetSymbolAddress((void**)&KE, g_KE);
    cudaGetSymbolAddress((void**)&VF, g_VF);
    cudaGetSymbolAddress((void**)&SS, g_SS);

    const long PB = (long)DIMD*KPROJ;   // per-batch compressed stride
    const long XB = (long)SEQ*DIMD;     // per-batch x stride

    // sumE | sumF
    colsum_k<<<2, 256>>>(E, F, SS);

    // Q = x @ Wq + bq   [16384,1024]
    sgemm<128,128,16,false,1,8,8><<<dim3(DIMD/128, MTOT/128, 1), 256>>>(
        x, Wq, Q, MTOT, DIMD, DIMD, 0, 0, 0, nullptr, bq);

    // XE[b] = x[b]^T @ E, XF[b] = x[b]^T @ F   [1024,256] each
    sgemm<64,64,16,true,0,4,4><<<dim3(KPROJ/64, DIMD/64, NB), 256>>>(
        x, E, XE, DIMD, KPROJ, SEQ, XB, 0, PB, nullptr, nullptr);
    sgemm<64,64,16,true,0,4,4><<<dim3(KPROJ/64, DIMD/64, NB), 256>>>(
        x, F, XF, DIMD, KPROJ, SEQ, XB, 0, PB, nullptr, nullptr);

    // KE[b] = Wk^T @ XE[b] + bk (x) sumE ;  VF[b] = Wv^T @ XF[b] + bv (x) sumF
    sgemm<64,64,16,true,2,4,4><<<dim3(KPROJ/64, DIMD/64, NB), 256>>>(
        Wk, XE, KE, DIMD, KPROJ, DIMD, 0, PB, PB, bk, SS);
    sgemm<64,64,16,true,2,4,4><<<dim3(KPROJ/64, DIMD/64, NB), 256>>>(
        Wv, XF, VF, DIMD, KPROJ, DIMD, 0, PB, PB, bv, SS + KPROJ);

    // fused attention -> AO
    static int smem_set = 0;
    size_t smem = (2*64*256 + 64*136)*sizeof(float);   // 165888 B
    if (!smem_set) {
        cudaFuncSetAttribute(attn_k, cudaFuncAttributeMaxDynamicSharedMemorySize,
                             (int)smem);
        smem_set = 1;
    }
    attn_k<<<dim3(SEQ/128, NHEAD, NB), 256, smem>>>(Q, KE, VF, AO);

    // out = AO @ Wo + bo
    sgemm<128,128,16,false,1,8,8><<<dim3(DIMD/128, MTOT/128, 1), 256>>>(
        AO, Wo, out, MTOT, DIMD, DIMD, 0, 0, 0, nullptr, bo);
}